// round 7
// baseline (speedup 1.0000x reference)
#include <cuda_runtime.h>
#include <math.h>

#define BATCHN 2048
#define SEQN   512
#define INPN   128
#define HIDN   256
#define OUTN   64
#define KTOT   384
#define ROWS   14          // batch rows per CTA; grid = 147 covers 2048
#define GRIDN  147
#define NTHR   512
#define CSS    20          // cs row stride (floats)
#define FEPS   1e-8f

typedef unsigned long long u64t;

__device__ float g_Wcat[KTOT * HIDN];                   // [384][256] lambda-folded
__device__ float g_H[(size_t)BATCHN * SEQN * HIDN];     // h history (1 GB scratch)

__device__ __forceinline__ u64t dup2(float a) {
    u64t r; asm("mov.b64 %0, {%1, %1};" : "=l"(r) : "f"(a)); return r;
}
__device__ __forceinline__ u64t pack2(float a, float b) {
    u64t r; asm("mov.b64 %0, {%1, %2};" : "=l"(r) : "f"(a), "f"(b)); return r;
}
__device__ __forceinline__ void ffma2(u64t& d, u64t a, u64t b) {
    asm("fma.rn.f32x2 %0, %1, %2, %0;" : "+l"(d) : "l"(a), "l"(b));
}
__device__ __forceinline__ float lo2(u64t v) { return __uint_as_float((unsigned)v); }
__device__ __forceinline__ float hi2(u64t v) { return __uint_as_float((unsigned)(v >> 32)); }

__global__ void prep_kernel(const float* __restrict__ Win, const float* __restrict__ Wrec,
                            const float* __restrict__ li,  const float* __restrict__ lr) {
    int k = blockIdx.x, j = threadIdx.x;
    g_Wcat[k * HIDN + j] = (k < HIDN) ? lr[j] * Wrec[k * HIDN + j]
                                      : li[j] * Win[(k - HIDN) * HIDN + j];
}

__global__ void __launch_bounds__(NTHR, 1) nlnn_main(
    const float* __restrict__ x,         // [B,S,128]
    const float* __restrict__ h_init,    // [B,256]
    const float* __restrict__ alpha_raw, // [256]
    float* __restrict__ hfin)
{
    extern __shared__ float smem[];
    float* cs    = smem;                 // [384][CSS]: k<256 h, k>=256 x
    float* vpart = smem + KTOT * CSS;    // [4][ROWS][256]

    const int tid = threadIdx.x;
    const int b0  = blockIdx.x * ROWS;
    const int rowsHere = (BATCHN - b0 < ROWS) ? (BATCHN - b0) : ROWS;

    // GEMM mapping: 64 jg (4 cols = 2 col-pairs) x 2 rg (7 rows) x 4 kg (96 k)
    const int jg = tid & 63, rg = (tid >> 6) & 1, kg = tid >> 7;
    const int j4 = jg * 4, r0 = rg * 7, kbeg = kg * 96;

    const int w = tid >> 5, lane = tid & 31;     // warp w <-> batch row w
    const bool act = (w < rowsHere);
    const int rowIdx = act ? (b0 + w) : (BATCHN - 1);

    float hh[8], al[8];
#pragma unroll
    for (int i = 0; i < 8; ++i) {
        int j = lane + 32 * i;
        hh[i] = h_init[(size_t)rowIdx * HIDN + j];
        al[i] = 1.0f / (1.0f + expf(-alpha_raw[j]));
        if (w < ROWS) cs[j * CSS + w] = hh[i];
    }

    float xr[4];
#pragma unroll
    for (int i = 0; i < 4; ++i)
        xr[i] = x[(size_t)rowIdx * SEQN * INPN + lane + 32 * i];

    for (int t = 0; t < SEQN; ++t) {
        if (w < ROWS) {
#pragma unroll
            for (int i = 0; i < 4; ++i)
                cs[(HIDN + lane + 32 * i) * CSS + w] = xr[i];
        }
        __syncthreads();                                   // S1: cs complete

        // ---- phase A: 7 rows x 2 col-pairs, this thread's K-quarter ----
        u64t acc[7][2];
#pragma unroll
        for (int p = 0; p < 7; ++p) { acc[p][0] = 0ull; acc[p][1] = 0ull; }

        const float* wp = g_Wcat + (size_t)kbeg * HIDN + j4;
        const float* cp = cs + kbeg * CSS + r0;
#pragma unroll 6
        for (int kk = 0; kk < 96; ++kk) {
            float4 wv = *(const float4*)(wp + (size_t)kk * HIDN);
            u64t wlo = pack2(wv.x, wv.y);
            u64t whi = pack2(wv.z, wv.w);
            const float* hp = cp + kk * CSS;
#pragma unroll
            for (int p = 0; p < 7; ++p) {
                u64t hb = dup2(hp[p]);
                ffma2(acc[p][0], wlo, hb);
                ffma2(acc[p][1], whi, hb);
            }
        }
        {
            float* vp = vpart + (size_t)(kg * ROWS + r0) * HIDN + j4;
#pragma unroll
            for (int p = 0; p < 7; ++p) {
                *(float4*)(vp + (size_t)p * HIDN) =
                    make_float4(lo2(acc[p][0]), hi2(acc[p][0]),
                                lo2(acc[p][1]), hi2(acc[p][1]));
            }
        }
        __syncthreads();                                   // S2: partials ready

        // ---- phase B: warp w owns row w ----
        const int wv_ = (w < ROWS) ? w : 0;                // safe index for inactive warps
        float vv[8], ssq = 0.f, hsq = 0.f, dtr = 0.f;
#pragma unroll
        for (int i = 0; i < 8; ++i) {
            int j = lane + 32 * i;
            float s = vpart[(0 * ROWS + wv_) * HIDN + j]
                    + vpart[(1 * ROWS + wv_) * HIDN + j]
                    + vpart[(2 * ROWS + wv_) * HIDN + j]
                    + vpart[(3 * ROWS + wv_) * HIDN + j];
            vv[i] = s;
            ssq = fmaf(s, s, ssq);
            hsq = fmaf(hh[i], hh[i], hsq);
            dtr = fmaf(hh[i], s, dtr);
        }
#pragma unroll
        for (int d = 16; d > 0; d >>= 1) {
            ssq += __shfl_xor_sync(0xffffffffu, ssq, d);
            hsq += __shfl_xor_sync(0xffffffffu, hsq, d);
            dtr += __shfl_xor_sync(0xffffffffu, dtr, d);
        }
        float ninv = 1.0f / (sqrtf(ssq) + FEPS);
        float hinv = 1.0f / (sqrtf(hsq) + FEPS);
        float dot  = dtr * ninv * hinv;
        dot = fminf(fmaxf(dot, -1.0f + FEPS), 1.0f - FEPS);
        float theta  = acosf(dot);
        float st     = __sinf(theta);
        float inv_st = 1.0f / (st + FEPS);
        bool  mask   = (st > FEPS);

        float res[8], rsq = 0.f;
#pragma unroll
        for (int i = 0; i < 8; ++i) {
            float hn = vv[i] * ninv;
            float ht = hh[i] * hinv;
            float ct = __sinf((1.0f - al[i]) * theta) * inv_st;
            float cn = __sinf(al[i] * theta) * inv_st;
            float r  = fmaf(ct, ht, cn * hn);
            r = mask ? r : hn;
            res[i] = r;
            rsq = fmaf(r, r, rsq);
        }
#pragma unroll
        for (int d = 16; d > 0; d >>= 1)
            rsq += __shfl_xor_sync(0xffffffffu, rsq, d);
        float rinv = 1.0f / (sqrtf(rsq) + FEPS);

        float* hrow = g_H + ((size_t)rowIdx * SEQN + t) * HIDN;
#pragma unroll
        for (int i = 0; i < 8; ++i) {
            hh[i] = res[i] * rinv;
            if (w < ROWS) cs[(lane + 32 * i) * CSS + w] = hh[i];
            if (act)      hrow[lane + 32 * i] = hh[i];
        }

        if (t + 1 < SEQN) {
#pragma unroll
            for (int i = 0; i < 4; ++i)
                xr[i] = x[((size_t)rowIdx * SEQN + t + 1) * INPN + lane + 32 * i];
        }
        // next S1 orders cs writes before phase A reads
    }

    if (hfin && act) {
#pragma unroll
        for (int i = 0; i < 8; ++i)
            hfin[(size_t)rowIdx * HIDN + lane + 32 * i] = hh[i];
    }
}

// out[row][c] = s_z * sum_j H[row][j]*Wout[j][c]
#define OB_ROWS 64
#define HSTR    68
__global__ void __launch_bounds__(256, 2) nlnn_out(
    const float* __restrict__ Wout, const float* __restrict__ s_z_p,
    float* __restrict__ outp)
{
    extern __shared__ float sh[];                     // [256][HSTR]
    const int tid = threadIdx.x;
    const size_t row0 = (size_t)blockIdx.x * OB_ROWS;

#pragma unroll 8
    for (int i = 0; i < OB_ROWS; ++i)
        sh[tid * HSTR + i] = g_H[(row0 + i) * HIDN + tid];
    __syncthreads();

    const int c = tid & 63, rb = (tid >> 6) * 16;
    const float sz = s_z_p[0];

    u64t acc[8];
#pragma unroll
    for (int p = 0; p < 8; ++p) acc[p] = 0ull;

#pragma unroll 4
    for (int j = 0; j < HIDN; ++j) {
        u64t b = dup2(Wout[j * OUTN + c]);
        const float* hp = sh + j * HSTR + rb;
        ulonglong2 hA = *(const ulonglong2*)(hp);
        ulonglong2 hB = *(const ulonglong2*)(hp + 4);
        ulonglong2 hC = *(const ulonglong2*)(hp + 8);
        ulonglong2 hD = *(const ulonglong2*)(hp + 12);
        ffma2(acc[0], hA.x, b); ffma2(acc[1], hA.y, b);
        ffma2(acc[2], hB.x, b); ffma2(acc[3], hB.y, b);
        ffma2(acc[4], hC.x, b); ffma2(acc[5], hC.y, b);
        ffma2(acc[6], hD.x, b); ffma2(acc[7], hD.y, b);
    }
#pragma unroll
    for (int p = 0; p < 8; ++p) {
        size_t r = row0 + rb + 2 * p;
        outp[r * OUTN + c]       = sz * lo2(acc[p]);
        outp[(r + 1) * OUTN + c] = sz * hi2(acc[p]);
    }
}

extern "C" void kernel_launch(void* const* d_in, const int* in_sizes, int n_in,
                              void* d_out, int out_size) {
    const float* x      = (const float*)d_in[0];
    const float* h_init = (const float*)d_in[1];
    const float* Win    = (const float*)d_in[2];
    const float* Wrec   = (const float*)d_in[3];
    const float* Wout   = (const float*)d_in[4];
    const float* li     = (const float*)d_in[5];
    const float* lr     = (const float*)d_in[6];
    const float* sz     = (const float*)d_in[7];
    const float* ar     = (const float*)d_in[8];

    float* outp = (float*)d_out;
    long long main_elems = (long long)BATCHN * SEQN * OUTN;
    float* hfin = nullptr;
    if ((long long)out_size >= main_elems + (long long)BATCHN * HIDN)
        hfin = outp + main_elems;

    int smem_main = (KTOT * CSS + 4 * ROWS * HIDN) * (int)sizeof(float);
    int smem_out  = (HIDN * HSTR) * (int)sizeof(float);
    cudaFuncSetAttribute(nlnn_main, cudaFuncAttributeMaxDynamicSharedMemorySize, smem_main);
    cudaFuncSetAttribute(nlnn_out,  cudaFuncAttributeMaxDynamicSharedMemorySize, smem_out);

    prep_kernel<<<KTOT, HIDN>>>(Win, Wrec, li, lr);
    nlnn_main<<<GRIDN, NTHR, smem_main>>>(x, h_init, ar, hfin);
    nlnn_out<<<(BATCHN * SEQN) / OB_ROWS, 256, smem_out>>>(Wout, sz, outp);
}

// round 10
// speedup vs baseline: 1.2754x; 1.2754x over previous
#include <cuda_runtime.h>
#include <math.h>

#define BATCHN 2048
#define SEQN   512
#define INPN   128
#define HIDN   256
#define OUTN   64
#define KTOT   384
#define ROWS   14          // batch rows per CTA; grid = 147 -> one CTA per SM
#define GRIDN  147
#define NTHR   512
#define CSS    20          // cs row stride (floats): 16B-aligned, 4-way-conflict STS
#define FEPS   1e-8f

typedef unsigned long long u64t;

__device__ float g_Wcat[KTOT * HIDN];                   // [384][256] lambda-folded
__device__ float g_H[(size_t)BATCHN * SEQN * HIDN];     // h history (1 GB scratch)

__device__ __forceinline__ u64t dup2(float a) {
    u64t r; asm("mov.b64 %0, {%1, %1};" : "=l"(r) : "f"(a)); return r;
}
__device__ __forceinline__ void ffma2(u64t& d, u64t a, u64t b) {
    asm("fma.rn.f32x2 %0, %1, %2, %0;" : "+l"(d) : "l"(a), "l"(b));
}
__device__ __forceinline__ float lo2(u64t v) { return __uint_as_float((unsigned)v); }
__device__ __forceinline__ float hi2(u64t v) { return __uint_as_float((unsigned)(v >> 32)); }

__global__ void prep_kernel(const float* __restrict__ Win, const float* __restrict__ Wrec,
                            const float* __restrict__ li,  const float* __restrict__ lr) {
    int k = blockIdx.x, j = threadIdx.x;
    g_Wcat[k * HIDN + j] = (k < HIDN) ? lr[j] * Wrec[k * HIDN + j]
                                      : li[j] * Win[(k - HIDN) * HIDN + j];
}

__global__ void __launch_bounds__(NTHR, 1) nlnn_main(
    const float* __restrict__ x,         // [B,S,128]
    const float* __restrict__ h_init,    // [B,256]
    const float* __restrict__ alpha_raw, // [256]
    float* __restrict__ hfin)
{
    extern __shared__ float smem[];
    float* cs    = smem;                 // [384][CSS]: k<256 h, k>=256 x (rows 0..13)
    float* vpart = smem + KTOT * CSS;    // [4][ROWS][256]

    const int tid = threadIdx.x;
    const int b0  = blockIdx.x * ROWS;
    const int rowsHere = (BATCHN - b0 < ROWS) ? (BATCHN - b0) : ROWS;

    // GEMM mapping: 128 jg (2 cols) x 4 kg (96 k each); every thread does all 14 rows
    const int jg = tid & 127, kg = tid >> 7;
    const int j2 = jg * 2, kbeg = kg * 96;

    const int w = tid >> 5, lane = tid & 31;     // warp w <-> batch row w
    const bool act = (w < rowsHere);
    const int rowIdx = act ? (b0 + w) : (BATCHN - 1);

    float hh[8], al[8];
#pragma unroll
    for (int i = 0; i < 8; ++i) {
        int j = lane + 32 * i;
        hh[i] = h_init[(size_t)rowIdx * HIDN + j];
        al[i] = 1.0f / (1.0f + expf(-alpha_raw[j]));
        if (w < ROWS) cs[j * CSS + w] = hh[i];
    }

    float xr[4];
#pragma unroll
    for (int i = 0; i < 4; ++i)
        xr[i] = x[(size_t)rowIdx * SEQN * INPN + lane + 32 * i];

    for (int t = 0; t < SEQN; ++t) {
        if (w < ROWS) {
#pragma unroll
            for (int i = 0; i < 4; ++i)
                cs[(HIDN + lane + 32 * i) * CSS + w] = xr[i];
        }
        __syncthreads();                                   // S1: cs complete

        // ---- phase A: 7 row-pairs x 2 cols, this thread's K-quarter ----
        u64t acc[7][2];
#pragma unroll
        for (int p = 0; p < 7; ++p) { acc[p][0] = 0ull; acc[p][1] = 0ull; }

        const float* wp = g_Wcat + (size_t)kbeg * HIDN + j2;
        const float* cp = cs + kbeg * CSS;
#pragma unroll 8
        for (int kk = 0; kk < 96; ++kk) {
            float2 wv = *(const float2*)(wp + (size_t)kk * HIDN);
            const float* hp = cp + kk * CSS;
            ulonglong2 ha = *(const ulonglong2*)(hp);      // row-pairs 0,1
            ulonglong2 hb = *(const ulonglong2*)(hp + 4);  // row-pairs 2,3
            ulonglong2 hc = *(const ulonglong2*)(hp + 8);  // row-pairs 4,5
            u64t       hd = *(const u64t*)(hp + 12);       // row-pair 6
            u64t c0 = dup2(wv.x), c1 = dup2(wv.y);
            ffma2(acc[0][0], ha.x, c0); ffma2(acc[0][1], ha.x, c1);
            ffma2(acc[1][0], ha.y, c0); ffma2(acc[1][1], ha.y, c1);
            ffma2(acc[2][0], hb.x, c0); ffma2(acc[2][1], hb.x, c1);
            ffma2(acc[3][0], hb.y, c0); ffma2(acc[3][1], hb.y, c1);
            ffma2(acc[4][0], hc.x, c0); ffma2(acc[4][1], hc.x, c1);
            ffma2(acc[5][0], hc.y, c0); ffma2(acc[5][1], hc.y, c1);
            ffma2(acc[6][0], hd,   c0); ffma2(acc[6][1], hd,   c1);
        }
        {
            float* vp = vpart + (size_t)kg * ROWS * HIDN + j2;
#pragma unroll
            for (int p = 0; p < 7; ++p) {
                *(float2*)(vp + (size_t)(2 * p) * HIDN) =
                    make_float2(lo2(acc[p][0]), lo2(acc[p][1]));
                *(float2*)(vp + (size_t)(2 * p + 1) * HIDN) =
                    make_float2(hi2(acc[p][0]), hi2(acc[p][1]));
            }
        }
        __syncthreads();                                   // S2: partials ready

        // ---- phase B: warp w owns row w ----
        const int wv_ = (w < ROWS) ? w : 0;
        float vv[8], ssq = 0.f, hsq = 0.f, dtr = 0.f;
#pragma unroll
        for (int i = 0; i < 8; ++i) {
            int j = lane + 32 * i;
            float s = vpart[(0 * ROWS + wv_) * HIDN + j]
                    + vpart[(1 * ROWS + wv_) * HIDN + j]
                    + vpart[(2 * ROWS + wv_) * HIDN + j]
                    + vpart[(3 * ROWS + wv_) * HIDN + j];
            vv[i] = s;
            ssq = fmaf(s, s, ssq);
            hsq = fmaf(hh[i], hh[i], hsq);
            dtr = fmaf(hh[i], s, dtr);
        }
#pragma unroll
        for (int d = 16; d > 0; d >>= 1) {
            ssq += __shfl_xor_sync(0xffffffffu, ssq, d);
            hsq += __shfl_xor_sync(0xffffffffu, hsq, d);
            dtr += __shfl_xor_sync(0xffffffffu, dtr, d);
        }
        float ninv = 1.0f / (sqrtf(ssq) + FEPS);
        float hinv = 1.0f / (sqrtf(hsq) + FEPS);
        float dot  = dtr * ninv * hinv;
        dot = fminf(fmaxf(dot, -1.0f + FEPS), 1.0f - FEPS);
        float theta  = acosf(dot);
        float st     = __sinf(theta);
        float inv_st = 1.0f / (st + FEPS);
        bool  mask   = (st > FEPS);

        float res[8], rsq = 0.f;
#pragma unroll
        for (int i = 0; i < 8; ++i) {
            float hn = vv[i] * ninv;
            float ht = hh[i] * hinv;
            float ct = __sinf((1.0f - al[i]) * theta) * inv_st;
            float cn = __sinf(al[i] * theta) * inv_st;
            float r  = fmaf(ct, ht, cn * hn);
            r = mask ? r : hn;
            res[i] = r;
            rsq = fmaf(r, r, rsq);
        }
#pragma unroll
        for (int d = 16; d > 0; d >>= 1)
            rsq += __shfl_xor_sync(0xffffffffu, rsq, d);
        float rinv = 1.0f / (sqrtf(rsq) + FEPS);

        float* hrow = g_H + ((size_t)rowIdx * SEQN + t) * HIDN;
#pragma unroll
        for (int i = 0; i < 8; ++i) {
            hh[i] = res[i] * rinv;
            if (w < ROWS) cs[(lane + 32 * i) * CSS + w] = hh[i];
            if (act)      hrow[lane + 32 * i] = hh[i];
        }

        if (t + 1 < SEQN) {
#pragma unroll
            for (int i = 0; i < 4; ++i)
                xr[i] = x[((size_t)rowIdx * SEQN + t + 1) * INPN + lane + 32 * i];
        }
        // next S1 orders cs writes before phase A reads
    }

    if (hfin && act) {
#pragma unroll
        for (int i = 0; i < 8; ++i)
            hfin[(size_t)rowIdx * HIDN + lane + 32 * i] = hh[i];
    }
}

// out[row][c] = s_z * sum_j H[row][j]*Wout[j][c]
#define OB_ROWS 64
#define HSTR    68
__global__ void __launch_bounds__(256, 2) nlnn_out(
    const float* __restrict__ Wout, const float* __restrict__ s_z_p,
    float* __restrict__ outp)
{
    extern __shared__ float sh[];                     // [256][HSTR]
    const int tid = threadIdx.x;
    const size_t row0 = (size_t)blockIdx.x * OB_ROWS;

#pragma unroll 8
    for (int i = 0; i < OB_ROWS; ++i)
        sh[tid * HSTR + i] = g_H[(row0 + i) * HIDN + tid];
    __syncthreads();

    const int c = tid & 63, rb = (tid >> 6) * 16;
    const float sz = s_z_p[0];

    u64t acc[8];
#pragma unroll
    for (int p = 0; p < 8; ++p) acc[p] = 0ull;

#pragma unroll 4
    for (int j = 0; j < HIDN; ++j) {
        u64t b = dup2(Wout[j * OUTN + c]);
        const float* hp = sh + j * HSTR + rb;
        ulonglong2 hA = *(const ulonglong2*)(hp);
        ulonglong2 hB = *(const ulonglong2*)(hp + 4);
        ulonglong2 hC = *(const ulonglong2*)(hp + 8);
        ulonglong2 hD = *(const ulonglong2*)(hp + 12);
        ffma2(acc[0], hA.x, b); ffma2(acc[1], hA.y, b);
        ffma2(acc[2], hB.x, b); ffma2(acc[3], hB.y, b);
        ffma2(acc[4], hC.x, b); ffma2(acc[5], hC.y, b);
        ffma2(acc[6], hD.x, b); ffma2(acc[7], hD.y, b);
    }
#pragma unroll
    for (int p = 0; p < 8; ++p) {
        size_t r = row0 + rb + 2 * p;
        outp[r * OUTN + c]       = sz * lo2(acc[p]);
        outp[(r + 1) * OUTN + c] = sz * hi2(acc[p]);
    }
}

extern "C" void kernel_launch(void* const* d_in, const int* in_sizes, int n_in,
                              void* d_out, int out_size) {
    const float* x      = (const float*)d_in[0];
    const float* h_init = (const float*)d_in[1];
    const float* Win    = (const float*)d_in[2];
    const float* Wrec   = (const float*)d_in[3];
    const float* Wout   = (const float*)d_in[4];
    const float* li     = (const float*)d_in[5];
    const float* lr     = (const float*)d_in[6];
    const float* sz     = (const float*)d_in[7];
    const float* ar     = (const float*)d_in[8];

    float* outp = (float*)d_out;
    long long main_elems = (long long)BATCHN * SEQN * OUTN;
    float* hfin = nullptr;
    if ((long long)out_size >= main_elems + (long long)BATCHN * HIDN)
        hfin = outp + main_elems;

    int smem_main = (KTOT * CSS + 4 * ROWS * HIDN) * (int)sizeof(float);
    int smem_out  = (HIDN * HSTR) * (int)sizeof(float);
    cudaFuncSetAttribute(nlnn_main, cudaFuncAttributeMaxDynamicSharedMemorySize, smem_main);
    cudaFuncSetAttribute(nlnn_out,  cudaFuncAttributeMaxDynamicSharedMemorySize, smem_out);

    prep_kernel<<<KTOT, HIDN>>>(Win, Wrec, li, lr);
    nlnn_main<<<GRIDN, NTHR, smem_main>>>(x, h_init, ar, hfin);
    nlnn_out<<<(BATCHN * SEQN) / OB_ROWS, 256, smem_out>>>(Wout, sz, outp);
}